// round 17
// baseline (speedup 1.0000x reference)
#include <cuda_runtime.h>
#include <cuda_bf16.h>

#define N 8192
#define ROWLEN 85
#define NCLS 80
#define CAP 256
#define MW 8               // CAP/32 suppression-mask words
#define FT 1024            // threads per block
#define NBLK 144           // 80 NMS + 64 rank; single wave, 1 block/SM
#define RB 64              // rank blocks (ids 80..143)
#define BINS 16384         // bin = (key>>16) - 0xC080  (scores in [0,1))
#define RCAP 512           // max rows a rank block can own (128 + max bin size)

__device__ unsigned g_skey[N];          // ~float_bits(score); asc == score desc
__device__ unsigned g_pack[N];          // row<<7 | cat
__device__ unsigned g_hist[BINS];       // bin counts (reset in P3)
__device__ int g_rank[N];               // row -> global sorted position
__device__ unsigned long long g_tick;   // monotone ticket counter (epochs)
__device__ unsigned long long g_c1;     // P1 done (144)
__device__ unsigned long long g_c2;     // P2 done (144)

struct NmsShared {
    unsigned long long keys[CAP];    // compacted (unsorted)
    unsigned long long skeys[CAP];   // counting-sorted (persists across B2)
    float4 box[CAP];
    float area[CAP];
    unsigned mask[(CAP + 1) * MW];   // +1 row: merge prefetch overshoot
    unsigned sup[MW];                // suppression bits (persists across B2)
    int cnt;
};

struct RankShared {
    unsigned prefix[BINS];           // local exclusive bin prefix (64 KB)
    unsigned long long list[RCAP];   // (key<<32)|row for owned bins
    int srow[RCAP];
    int srk[RCAP];
    int cnt;
};

// arrive + spin barrier on a monotone counter (replay-safe: epoch-scaled
// targets). Thread-0 fence after __syncthreads suffices (fence cumulativity).
__device__ __forceinline__ void gsync(unsigned long long* c, unsigned long long tgt) {
    __syncthreads();
    if (threadIdx.x == 0) {
        __threadfence();
        atomicAdd(c, 1ull);
        while (*(volatile unsigned long long*)c < tgt) {}
        __threadfence();
    }
    __syncthreads();
}

__global__ void __launch_bounds__(FT, 1)
yolonms_kernel(const float* __restrict__ X, float* __restrict__ out) {
    extern __shared__ __align__(16) char sm[];
    __shared__ unsigned long long s_ep;
    __shared__ unsigned s_ws[32];

    int t = threadIdx.x, b = blockIdx.x;
    int lane = t & 31, w = t >> 5;

    if (t == 0) s_ep = atomicAdd(&g_tick, 1ull) / NBLK;
    __syncthreads();
    unsigned long long ep = s_ep;

    // ---------------- Phase 1: score + histogram (all blocks) ----------------
    {
        int r0 = b * 32 + w;
        int r1 = r0 + NBLK * 32;
        float a0 = -1.f, a1 = -1.f, a2 = -1.f, c0 = -1.f, c1 = -1.f, c2 = -1.f;
        float o0 = 0.f, o1 = 0.f;
        if (r0 < N) {
            const float* row = X + (long)r0 * ROWLEN;
            a0 = row[5 + lane]; a1 = row[37 + lane];
            a2 = (lane < 16) ? row[69 + lane] : -1.0f;
            o0 = row[4];
        }
        if (r1 < N) {
            const float* row = X + (long)r1 * ROWLEN;
            c0 = row[5 + lane]; c1 = row[37 + lane];
            c2 = (lane < 16) ? row[69 + lane] : -1.0f;
            o1 = row[4];
        }
        #pragma unroll
        for (int it = 0; it < 2; it++) {
            int r = it ? r1 : r0;
            if (r >= N) continue;
            float v0 = it ? c0 : a0, v1 = it ? c1 : a1, v2 = it ? c2 : a2;
            float obj = it ? o1 : o0;
            float best = v0; int bi = lane;
            if (v1 > best) { best = v1; bi = lane + 32; }
            if (v2 > best) { best = v2; bi = lane + 64; }
            unsigned bb = __float_as_uint(best);            // nonneg -> monotone
            unsigned vmax = __reduce_max_sync(0xffffffffu, bb);
            int cand = (bb == vmax) ? bi : 0x7fffffff;      // smallest idx wins ties
            int bimin = __reduce_min_sync(0xffffffffu, cand);
            if (lane == 0) {
                float score = obj * __uint_as_float(vmax);  // in [0, 1)
                unsigned key = ~__float_as_uint(score);
                g_skey[r] = key;
                g_pack[r] = ((unsigned)r << 7) | (unsigned)bimin;
                unsigned bin = (key >> 16) - 0xC080u;
                if (bin >= BINS) bin = BINS - 1;
                atomicAdd(&g_hist[bin], 1u);
            }
        }
    }
    gsync(&g_c1, (ep + 1) * NBLK);

    // ------- Phase 2: NMS blocks || rank blocks (rank + output copy) -------
    int m = 0;   // NMS class size, persists to P3
    if (b < NCLS) {
        // per-class greedy NMS. Class offsets in the reference make cross-
        // class IoU exactly 0, so suppression decomposes per class.
        NmsShared& S = *reinterpret_cast<NmsShared*>(sm);
        unsigned c = b;

        if (t == 0) S.cnt = 0;
        __syncthreads();

        unsigned pk[N / FT], sk[N / FT];
        #pragma unroll
        for (int q = 0; q < N / FT; q++) {
            pk[q] = g_pack[q * FT + t];
            sk[q] = g_skey[q * FT + t];
        }
        #pragma unroll
        for (int q = 0; q < N / FT; q++) {
            if ((pk[q] & 127u) == c) {
                int slot = atomicAdd(&S.cnt, 1);
                if (slot < CAP)
                    S.keys[slot] = ((unsigned long long)sk[q] << 32) | pk[q];
            }
        }
        __syncthreads();
        m = min(S.cnt, CAP);

        // counting sort: keys unique (row embedded) -> exact stable order
        if (t < m) {
            unsigned long long k = S.keys[t];
            int r = 0;
            for (int j = 0; j < m; j++) r += (S.keys[j] < k);
            S.skeys[r] = k;
        }
        __syncthreads();

        if (t < m) {
            int idx = (int)(((unsigned)(S.skeys[t] & 0xFFFFFFFFull)) >> 7);
            const float* row = X + (long)idx * ROWLEN;
            float x1 = row[0], y1 = row[1], x2 = row[2], y2 = row[3];
            S.box[t] = make_float4(x1, y1, x2, y2);
            S.area[t] = (x2 - x1) * (y2 - y1);
        }
        for (int p = t; p < (m + 1) * MW; p += FT) S.mask[p] = 0u;
        __syncthreads();

        // mask[i] = { j > i : IoU(i,j) > 0.5 } — parallel over 32 warps
        for (int i = w; i < m; i += FT / 32) {
            float4 bi = S.box[i];
            float ai = S.area[i];
            for (int j = i + 1 + lane; j < m; j += 32) {
                float4 bj = S.box[j];
                float xx1 = fmaxf(bi.x, bj.x);
                float yy1 = fmaxf(bi.y, bj.y);
                float xx2 = fminf(bi.z, bj.z);
                float yy2 = fminf(bi.w, bj.w);
                float ww = fmaxf(xx2 - xx1, 0.0f);
                float hh = fmaxf(yy2 - yy1, 0.0f);
                float inter = ww * hh;
                float iou = inter / (ai + S.area[j] - inter);
                if (iou > 0.5f) atomicOr(&S.mask[i * MW + (j >> 5)], 1u << (j & 31));
            }
        }
        __syncthreads();

        if (t == 0) {   // serial greedy bit-merge with unconditional prefetch
            unsigned sx[MW], pm[MW];
            #pragma unroll
            for (int q = 0; q < MW; q++) { sx[q] = 0u; pm[q] = S.mask[q]; }
            for (int i = 0; i < m; i++) {
                unsigned nm[MW];
                #pragma unroll
                for (int q = 0; q < MW; q++) nm[q] = S.mask[(i + 1) * MW + q];
                unsigned kept = ((sx[i >> 5] >> (i & 31)) & 1u) ^ 1u;
                unsigned sel = 0u - kept;
                #pragma unroll
                for (int q = 0; q < MW; q++) sx[q] |= (pm[q] & sel);
                #pragma unroll
                for (int q = 0; q < MW; q++) pm[q] = nm[q];
            }
            #pragma unroll
            for (int q = 0; q < MW; q++) S.sup[q] = sx[q];
        }
        __syncthreads();
        // S.skeys + S.sup stay live in smem for the P3 zeroing pass.
    } else {
        // ---- rank blocks: quantile-owned bins, zero global barriers ----
        // Block rb owns bin B iff prefix[B]>>7 == rb (128 ranks per block,
        // whole bins). Every row handled exactly once; load auto-balanced.
        int rb = b - NCLS;
        RankShared& R = *reinterpret_cast<RankShared*>(sm);

        // local exclusive prefix of all 16K bins (block scan, 16 bins/thread)
        unsigned h[BINS / FT];
        unsigned tsum = 0;
        int base = t * (BINS / FT);
        #pragma unroll
        for (int l = 0; l < BINS / FT; l++) { h[l] = g_hist[base + l]; tsum += h[l]; }
        unsigned incl = tsum;
        #pragma unroll
        for (int off = 1; off < 32; off <<= 1) {
            unsigned u = __shfl_up_sync(0xffffffffu, incl, off);
            if (lane >= off) incl += u;
        }
        if (lane == 31) s_ws[w] = incl;
        __syncthreads();
        if (t < 32) {
            unsigned x = s_ws[lane];
            #pragma unroll
            for (int off = 1; off < 32; off <<= 1) {
                unsigned u = __shfl_up_sync(0xffffffffu, x, off);
                if (lane >= off) x += u;
            }
            s_ws[lane] = x;
        }
        __syncthreads();
        unsigned run = ((w > 0) ? s_ws[w - 1] : 0u) + incl - tsum;
        #pragma unroll
        for (int l = 0; l < BINS / FT; l++) { R.prefix[base + l] = run; run += h[l]; }
        if (t == 0) R.cnt = 0;
        __syncthreads();

        // select rows whose bin this block owns (front-loaded key burst)
        unsigned sk2[N / FT];
        #pragma unroll
        for (int q = 0; q < N / FT; q++) sk2[q] = g_skey[q * FT + t];
        #pragma unroll
        for (int q = 0; q < N / FT; q++) {
            unsigned key = sk2[q];
            unsigned bin = (key >> 16) - 0xC080u;
            if (bin >= BINS) bin = BINS - 1;
            if ((int)(R.prefix[bin] >> 7) == rb) {
                int slot = atomicAdd(&R.cnt, 1);
                if (slot < RCAP)
                    R.list[slot] = ((unsigned long long)key << 32) | (unsigned)(q * FT + t);
            }
        }
        __syncthreads();
        int c = min(R.cnt, RCAP);

        // exact rank: prefix[bin] + #{same-bin entries smaller in (key,row)}
        if (t < c) {
            unsigned long long k64 = R.list[t];
            unsigned key = (unsigned)(k64 >> 32);
            int row = (int)(k64 & 0xFFFFFFFFull);
            unsigned bin = (key >> 16) - 0xC080u;
            if (bin >= BINS) bin = BINS - 1;
            int cnt2 = 0;
            for (int j = 0; j < c; j++) {
                unsigned long long kj = R.list[j];
                unsigned keyj = (unsigned)(kj >> 32);
                unsigned binj = (keyj >> 16) - 0xC080u;
                if (binj >= BINS) binj = BINS - 1;
                cnt2 += (binj == bin && kj < k64);
            }
            int rk = (int)R.prefix[bin] + cnt2;
            R.srow[t] = row;
            R.srk[t] = rk;
            g_rank[row] = rk;
        }
        __syncthreads();

        // warp-per-element copy X[row] -> out[rank] (permutation: each out
        // row written exactly once across all rank blocks)
        for (int e = w; e < c; e += FT / 32) {
            const float* src = X + (long)R.srow[e] * ROWLEN;
            float* dst = out + (long)R.srk[e] * ROWLEN;
            #pragma unroll
            for (int c2 = lane; c2 < ROWLEN; c2 += 32) dst[c2] = src[c2];
        }
    }

    gsync(&g_c2, (ep + 1) * NBLK);

    // ------ Phase 3 (tiny): NMS blocks zero suppressed rows; reset hist ------
    {
        int i = b * FT + t;
        if (i < BINS) g_hist[i] = 0u;
    }
    if (b < NCLS) {
        NmsShared& S = *reinterpret_cast<NmsShared*>(sm);
        for (int i = w; i < m; i += FT / 32) {          // warp per class entry
            if ((S.sup[i >> 5] >> (i & 31)) & 1u) {
                int idx = (int)(((unsigned)(S.skeys[i] & 0xFFFFFFFFull)) >> 7);
                int rk = g_rank[idx];                    // plain load, post-B2
                float* dst = out + (long)rk * ROWLEN;
                #pragma unroll
                for (int c2 = lane; c2 < ROWLEN; c2 += 32) dst[c2] = 0.0f;
            }
        }
    }
}

// ---------------------------------------------------------------------------
extern "C" void kernel_launch(void* const* d_in, const int* in_sizes, int n_in,
                              void* d_out, int out_size) {
    const float* X = (const float*)d_in[0];
    float* out = (float*)d_out;

    int nms_bytes = (int)sizeof(NmsShared);
    int rank_bytes = (int)sizeof(RankShared);
    int smem = nms_bytes > rank_bytes ? nms_bytes : rank_bytes;

    static int smem_set = 0;
    if (!smem_set) {
        cudaFuncSetAttribute(yolonms_kernel,
                             cudaFuncAttributeMaxDynamicSharedMemorySize, smem);
        smem_set = 1;
    }

    yolonms_kernel<<<NBLK, FT, smem>>>(X, out);
}